// round 7
// baseline (speedup 1.0000x reference)
#include <cuda_runtime.h>
#include <cuda_bf16.h>
#include <cuda_fp16.h>
#include <mma.h>
#include <cstdint>
#include <math.h>

using namespace nvcuda;

#define F 256
#define MAXN 100000
#define MAXE 3200000

// ---------------- device scratch ----------------
__device__ float g_H[(size_t)MAXN * F];         // SpMM1 output (fp32, read by GEMM2)
__device__ __half g_Xh[(size_t)MAXN * F];       // fp16 copy of current GEMM output
__device__ int   g_ptr[MAXN + 1];
__device__ int   g_cursor[MAXN + 1];
__device__ int   g_cols[MAXE];
__device__ float g_vals[MAXE];
__device__ int   g_bsum[256];
__device__ float g_sum[F], g_sumsq[F];
__device__ float g_a[F], g_b[F];
__device__ uint32_t g_Wt[2 * F * F];            // W1, W2 pre-rounded to tf32 bits

__device__ __forceinline__ uint32_t smem_u32(const void* p) {
    uint32_t a;
    asm("{ .reg .u64 t; cvta.to.shared.u64 t, %1; cvt.u32.u64 %0, t; }" : "=r"(a) : "l"(p));
    return a;
}
__device__ __forceinline__ float f2tf32f(float x) {
    uint32_t r;
    asm("cvt.rna.tf32.f32 %0, %1;" : "=r"(r) : "f"(x));
    return __uint_as_float(r);
}

// ---------------- CSR construction ----------------
__global__ void k_zero(int n) {
    int i = blockIdx.x * blockDim.x + threadIdx.x;
    if (i < n) g_ptr[i] = 0;
    if (i < F) { g_sum[i] = 0.f; g_sumsq[i] = 0.f; }
}
__global__ void k_hist(const int* __restrict__ rows, int E) {
    int e = blockIdx.x * blockDim.x + threadIdx.x;
    if (e < E) atomicAdd(&g_ptr[rows[e] + 1], 1);
}
__global__ void k_scan_block(int n) {
    __shared__ int sh[1024];
    int t = threadIdx.x;
    int gid = blockIdx.x * 1024 + t;
    int v = (gid < n) ? g_ptr[gid] : 0;
    sh[t] = v;
    __syncthreads();
    #pragma unroll
    for (int off = 1; off < 1024; off <<= 1) {
        int tv = (t >= off) ? sh[t - off] : 0;
        __syncthreads();
        sh[t] += tv;
        __syncthreads();
    }
    if (gid < n) g_ptr[gid] = sh[t];
    if (t == 1023) g_bsum[blockIdx.x] = sh[1023];
}
__global__ void k_scan_sums(int nb) {
    __shared__ int sh[128];
    int t = threadIdx.x;
    int v = (t < nb) ? g_bsum[t] : 0;
    sh[t] = v;
    __syncthreads();
    #pragma unroll
    for (int off = 1; off < 128; off <<= 1) {
        int tv = (t >= off) ? sh[t - off] : 0;
        __syncthreads();
        sh[t] += tv;
        __syncthreads();
    }
    if (t < nb) g_bsum[t] = (t == 0) ? 0 : sh[t - 1];
}
__global__ void k_scan_add(int n) {
    int gid = blockIdx.x * 1024 + threadIdx.x;
    if (gid < n) {
        int v = g_ptr[gid] + g_bsum[blockIdx.x];
        g_ptr[gid] = v;
        g_cursor[gid] = v;
    }
}
__global__ void k_scatter(const int* __restrict__ rows, const int* __restrict__ cols,
                          const float* __restrict__ vals, int E) {
    int e = blockIdx.x * blockDim.x + threadIdx.x;
    if (e < E) {
        int r = rows[e];
        int pos = atomicAdd(&g_cursor[r], 1);
        g_cols[pos] = cols[e];
        g_vals[pos] = vals[e];
    }
}

// ---------------- W pre-round to tf32 ----------------
__global__ void k_prep_w(const float* __restrict__ W1, const float* __restrict__ W2) {
    int i = blockIdx.x * blockDim.x + threadIdx.x;
    g_Wt[i]         = __float_as_uint(f2tf32f(W1[i]));
    g_Wt[i + F * F] = __float_as_uint(f2tf32f(W2[i]));
}

// ---------------- tf32 wmma GEMM, fp16 output only ----------------
#define ALD 36
#define BLD 264
#define ASZ (64 * ALD)
#define BSZ (32 * BLD)
#define STAGE_F (ASZ + BSZ)
#define EPLD 264

__device__ __forceinline__ void cp16(uint32_t dst, const void* src) {
    asm volatile("cp.async.ca.shared.global [%0], [%1], 16;" :: "r"(dst), "l"(src));
}

__global__ void __launch_bounds__(256)
k_gemm_wmma(const float* __restrict__ A, const uint32_t* __restrict__ Wt,
            __half* __restrict__ Ch, int M, int bnrelu) {
    extern __shared__ float sm[];
    int tid = threadIdx.x;
    int wid = tid >> 5;
    int warp_row = wid >> 2;
    int warp_col = wid & 3;
    int row0 = blockIdx.x * 64;

    wmma::fragment<wmma::accumulator, 16, 16, 8, float> acc[2][4];
    #pragma unroll
    for (int i = 0; i < 2; i++)
        #pragma unroll
        for (int j = 0; j < 4; j++) wmma::fill_fragment(acc[i][j], 0.f);

    int a_r0 = tid >> 3;
    int a_c0 = (tid & 7) * 4;
    int a_r1 = a_r0 + 32;

    float4 areg[2];
    auto load_A = [&](int k0) {
        int gr0 = row0 + a_r0, gr1 = row0 + a_r1;
        areg[0] = (gr0 < M) ? *(const float4*)(A + (size_t)gr0 * F + k0 * 32 + a_c0)
                            : make_float4(0.f, 0.f, 0.f, 0.f);
        areg[1] = (gr1 < M) ? *(const float4*)(A + (size_t)gr1 * F + k0 * 32 + a_c0)
                            : make_float4(0.f, 0.f, 0.f, 0.f);
        if (bnrelu) {
            int c = k0 * 32 + a_c0;
            float a0 = g_a[c], a1 = g_a[c + 1], a2 = g_a[c + 2], a3 = g_a[c + 3];
            float b0 = g_b[c], b1 = g_b[c + 1], b2 = g_b[c + 2], b3 = g_b[c + 3];
            #pragma unroll
            for (int i = 0; i < 2; i++) {
                areg[i].x = fmaxf(fmaf(areg[i].x, a0, b0), 0.f);
                areg[i].y = fmaxf(fmaf(areg[i].y, a1, b1), 0.f);
                areg[i].z = fmaxf(fmaf(areg[i].z, a2, b2), 0.f);
                areg[i].w = fmaxf(fmaf(areg[i].w, a3, b3), 0.f);
            }
        }
        #pragma unroll
        for (int i = 0; i < 2; i++) {
            areg[i].x = f2tf32f(areg[i].x);
            areg[i].y = f2tf32f(areg[i].y);
            areg[i].z = f2tf32f(areg[i].z);
            areg[i].w = f2tf32f(areg[i].w);
        }
    };
    auto sts_A = [&](float* As) {
        *(float4*)(As + a_r0 * ALD + a_c0) = areg[0];
        *(float4*)(As + a_r1 * ALD + a_c0) = areg[1];
    };
    auto cpB = [&](float* Bs, int k0) {
        uint32_t bbase = smem_u32(Bs);
        #pragma unroll
        for (int i = 0; i < 8; i++) {
            int idx = tid + i * 256;
            int r = idx >> 6;
            int c4 = (idx & 63) * 4;
            cp16(bbase + (uint32_t)(r * BLD + c4) * 4,
                 Wt + (size_t)(k0 * 32 + r) * F + c4);
        }
    };

    int buf = 0;
    load_A(0);
    sts_A(sm);
    cpB(sm + ASZ, 0);
    asm volatile("cp.async.commit_group;" ::: "memory");

    for (int k0 = 0; k0 < 8; k0++) {
        if (k0 < 7) load_A(k0 + 1);
        asm volatile("cp.async.wait_group 0;" ::: "memory");
        __syncthreads();
        float* As = sm + buf * STAGE_F;
        float* Bs = As + ASZ;
        if (k0 < 7) {
            float* Asn = sm + (buf ^ 1) * STAGE_F;
            sts_A(Asn);
            cpB(Asn + ASZ, k0 + 1);
            asm volatile("cp.async.commit_group;" ::: "memory");
        }
        #pragma unroll
        for (int kk = 0; kk < 4; kk++) {
            wmma::fragment<wmma::matrix_a, 16, 16, 8, wmma::precision::tf32, wmma::row_major> af[2];
            wmma::fragment<wmma::matrix_b, 16, 16, 8, wmma::precision::tf32, wmma::row_major> bf[4];
            #pragma unroll
            for (int i = 0; i < 2; i++)
                wmma::load_matrix_sync(af[i], As + (warp_row * 32 + i * 16) * ALD + kk * 8, ALD);
            #pragma unroll
            for (int j = 0; j < 4; j++)
                wmma::load_matrix_sync(bf[j], Bs + (kk * 8) * BLD + warp_col * 64 + j * 16, BLD);
            #pragma unroll
            for (int i = 0; i < 2; i++)
                #pragma unroll
                for (int j = 0; j < 4; j++)
                    wmma::mma_sync(acc[i][j], af[i], bf[j], acc[i][j]);
        }
        __syncthreads();
        buf ^= 1;
    }

    // epilogue: frags -> smem -> coalesced fp16 store only
    float* ep = sm;   // 64 x EPLD
    #pragma unroll
    for (int i = 0; i < 2; i++)
        #pragma unroll
        for (int j = 0; j < 4; j++)
            wmma::store_matrix_sync(ep + (size_t)(warp_row * 32 + i * 16) * EPLD + warp_col * 64 + j * 16,
                                    acc[i][j], EPLD, wmma::mem_row_major);
    __syncthreads();

    #pragma unroll
    for (int it = 0; it < 8; it++) {
        int idx = tid + it * 256;          // 2048 groups of 8 floats
        int r = idx >> 5;
        int g = idx & 31;
        int grow = row0 + r;
        if (grow < M) {
            float4 v0 = *(float4*)(ep + r * EPLD + g * 8);
            float4 v1 = *(float4*)(ep + r * EPLD + g * 8 + 4);
            __half2 h[4];
            h[0] = __floats2half2_rn(v0.x, v0.y);
            h[1] = __floats2half2_rn(v0.z, v0.w);
            h[2] = __floats2half2_rn(v1.x, v1.y);
            h[3] = __floats2half2_rn(v1.z, v1.w);
            *(uint4*)(Ch + (size_t)grow * F + g * 8) = *reinterpret_cast<uint4*>(h);
        }
    }
}

// ---------------- SpMM (all-fp16 sources) + optional fused BN stats ----------------
__global__ void __launch_bounds__(256)
k_spmm(const __half* __restrict__ Xh, float* __restrict__ Y, int Nn, int do_stats) {
    __shared__ float ssum[256], ssumsq[256];
    int tid = threadIdx.x;
    if (do_stats) {
        ssum[tid] = 0.f;
        ssumsq[tid] = 0.f;
        __syncthreads();
    }

    int gw = (blockIdx.x * 256 + tid) >> 5;
    int row = gw >> 1;
    int half = gw & 1;
    int lane = tid & 31;
    bool valid = (row < Nn);

    float4 acc = make_float4(0.f, 0.f, 0.f, 0.f);
    const __half* Xhh = Xh + half * 128;
    if (valid) {
        // self loop from the fp16 copy (L2-hot)
        uint2 u = *(const uint2*)(Xhh + (size_t)row * F + lane * 4);
        float2 f0 = __half22float2(*reinterpret_cast<const __half2*>(&u.x));
        float2 f1 = __half22float2(*reinterpret_cast<const __half2*>(&u.y));
        acc = make_float4(f0.x, f0.y, f1.x, f1.y);

        int e = g_ptr[row];
        int end = g_ptr[row + 1];
        while (e < end) {
            int m = end - e;
            int c = 0;
            float vv = 0.f;
            if (lane < m) { c = g_cols[e + lane]; vv = g_vals[e + lane]; }
            int cnt = m < 32 ? m : 32;
            #pragma unroll 4
            for (int j = 0; j < cnt; j++) {
                int cj = __shfl_sync(0xffffffffu, c, j);
                float vj = __shfl_sync(0xffffffffu, vv, j);
                uint2 un = *(const uint2*)(Xhh + (size_t)cj * F + lane * 4);
                float2 g0 = __half22float2(*reinterpret_cast<const __half2*>(&un.x));
                float2 g1 = __half22float2(*reinterpret_cast<const __half2*>(&un.y));
                acc.x = fmaf(vj, g0.x, acc.x);
                acc.y = fmaf(vj, g0.y, acc.y);
                acc.z = fmaf(vj, g1.x, acc.z);
                acc.w = fmaf(vj, g1.y, acc.w);
            }
            e += 32;
        }
        __stcs((float4*)(Y + (size_t)row * F + half * 128 + lane * 4), acc);
    }

    if (do_stats) {
        if (valid) {
            int cb = half * 128 + lane * 4;
            atomicAdd(&ssum[cb + 0], acc.x);
            atomicAdd(&ssum[cb + 1], acc.y);
            atomicAdd(&ssum[cb + 2], acc.z);
            atomicAdd(&ssum[cb + 3], acc.w);
            atomicAdd(&ssumsq[cb + 0], acc.x * acc.x);
            atomicAdd(&ssumsq[cb + 1], acc.y * acc.y);
            atomicAdd(&ssumsq[cb + 2], acc.z * acc.z);
            atomicAdd(&ssumsq[cb + 3], acc.w * acc.w);
        }
        __syncthreads();
        atomicAdd(&g_sum[tid], ssum[tid]);
        atomicAdd(&g_sumsq[tid], ssumsq[tid]);
    }
}

// ---------------- BN finalize ----------------
__global__ void k_finalize(int M, const float* __restrict__ gamma,
                           const float* __restrict__ beta) {
    int c = threadIdx.x;
    float invM = 1.f / (float)M;
    float m = g_sum[c] * invM;
    float var = g_sumsq[c] * invM - m * m;
    float r = rsqrtf(var + 1e-5f);
    float a = gamma[c] * r;
    g_a[c] = a;
    g_b[c] = beta[c] - m * a;
}

// ---------------- launch ----------------
extern "C" void kernel_launch(void* const* d_in, const int* in_sizes, int n_in,
                              void* d_out, int out_size) {
    const float* feature = (const float*)d_in[0];
    const int*   rows    = (const int*)d_in[1];
    const int*   cols    = (const int*)d_in[2];
    const float* vals    = (const float*)d_in[3];
    const float* W1      = (const float*)d_in[4];
    const float* W2      = (const float*)d_in[5];
    const float* gamma   = (const float*)d_in[6];
    const float* beta    = (const float*)d_in[7];
    float* out = (float*)d_out;

    int N_ = in_sizes[0] / F;
    int E_ = in_sizes[1];

    float* p_H;
    __half* p_Xh;
    uint32_t* p_Wt;
    cudaGetSymbolAddress((void**)&p_H, g_H);
    cudaGetSymbolAddress((void**)&p_Xh, g_Xh);
    cudaGetSymbolAddress((void**)&p_Wt, g_Wt);

    const int smem_bytes = 2 * STAGE_F * sizeof(float);
    cudaFuncSetAttribute(k_gemm_wmma, cudaFuncAttributeMaxDynamicSharedMemorySize, smem_bytes);

    static cudaStream_t s2 = nullptr;
    static cudaEvent_t evF = nullptr, evJ = nullptr;
    if (!s2) {
        cudaStreamCreateWithFlags(&s2, cudaStreamNonBlocking);
        cudaEventCreateWithFlags(&evF, cudaEventDisableTiming);
        cudaEventCreateWithFlags(&evJ, cudaEventDisableTiming);
    }

    int n_ptr = N_ + 1;
    int nb = (n_ptr + 1023) / 1024;
    int gtiles = (N_ + 63) / 64;
    int spmm_blocks = (2 * N_ * 32 + 255) / 256;

    // fork: CSR build concurrent with weight prep + GEMM1
    cudaEventRecord(evF, 0);
    cudaStreamWaitEvent(s2, evF, 0);

    k_zero<<<(n_ptr + 255) / 256, 256, 0, s2>>>(n_ptr);
    k_hist<<<(E_ + 255) / 256, 256, 0, s2>>>(rows, E_);
    k_scan_block<<<nb, 1024, 0, s2>>>(n_ptr);
    k_scan_sums<<<1, 128, 0, s2>>>(nb);
    k_scan_add<<<nb, 1024, 0, s2>>>(n_ptr);
    k_scatter<<<(E_ + 255) / 256, 256, 0, s2>>>(rows, cols, vals, E_);
    cudaEventRecord(evJ, s2);

    k_prep_w<<<F * F / 256, 256>>>(W1, W2);
    k_gemm_wmma<<<gtiles, 256, smem_bytes>>>(feature, p_Wt, p_Xh, N_, 0);

    cudaStreamWaitEvent(0, evJ, 0);

    // H = (A+I)@support  (fp16 gather, fp32 out) + fused BN stats
    k_spmm<<<spmm_blocks, 256>>>(p_Xh, p_H, N_, 1);
    k_finalize<<<1, 256>>>(N_, gamma, beta);
    // Y(fp16) = relu(BN(H)) @ W2
    k_gemm_wmma<<<gtiles, 256, smem_bytes>>>(p_H, p_Wt + F * F, p_Xh, N_, 1);
    // out = (A+I)@Y
    k_spmm<<<spmm_blocks, 256>>>(p_Xh, out, N_, 0);
}

// round 9
// speedup vs baseline: 1.0289x; 1.0289x over previous
#include <cuda_runtime.h>
#include <cuda_bf16.h>
#include <cuda_fp16.h>
#include <mma.h>
#include <cstdint>
#include <math.h>

using namespace nvcuda;

#define F 256
#define MAXN 100000
#define MAXE 3200000

// ---------------- device scratch ----------------
__device__ __half g_H16[(size_t)MAXN * F];      // SpMM1 output (fp16, read by GEMM2)
__device__ __half g_Xh[(size_t)MAXN * F];       // fp16 copy of current GEMM output
__device__ int   g_ptr[MAXN + 1];
__device__ int   g_cursor[MAXN + 1];
__device__ int   g_cols[MAXE];
__device__ float g_vals[MAXE];
__device__ int   g_bsum[256];
__device__ float g_stats[2 * F];                // [0:256) sum, [256:512) sumsq
__device__ float g_a[F], g_b[F];
__device__ uint32_t g_Wt[2 * F * F];            // W1, W2 pre-rounded to tf32 bits

__device__ __forceinline__ uint32_t smem_u32(const void* p) {
    uint32_t a;
    asm("{ .reg .u64 t; cvta.to.shared.u64 t, %1; cvt.u32.u64 %0, t; }" : "=r"(a) : "l"(p));
    return a;
}
__device__ __forceinline__ float f2tf32f(float x) {
    uint32_t r;
    asm("cvt.rna.tf32.f32 %0, %1;" : "=r"(r) : "f"(x));
    return __uint_as_float(r);
}
// L2 evict_last policy (per-thread, created once)
__device__ __forceinline__ uint64_t mk_policy_el() {
    uint64_t pol;
    asm volatile("createpolicy.fractional.L2::evict_last.b64 %0, 1.0;" : "=l"(pol));
    return pol;
}
// 8-byte gather load with cache-hint policy
__device__ __forceinline__ uint2 ldg_pol8(const void* p, uint64_t pol) {
    uint2 u;
    asm volatile("ld.global.nc.L2::cache_hint.v2.u32 {%0, %1}, [%2], %3;"
                 : "=r"(u.x), "=r"(u.y) : "l"(p), "l"(pol));
    return u;
}

// ---------------- CSR construction ----------------
__global__ void k_hist(const int* __restrict__ rows, int E) {
    int e = blockIdx.x * blockDim.x + threadIdx.x;
    if (e < E) atomicAdd(&g_ptr[__ldcs(rows + e) + 1], 1);
}
__global__ void k_scan_block(int n) {
    __shared__ int sh[1024];
    int t = threadIdx.x;
    int gid = blockIdx.x * 1024 + t;
    int v = (gid < n) ? g_ptr[gid] : 0;
    sh[t] = v;
    __syncthreads();
    #pragma unroll
    for (int off = 1; off < 1024; off <<= 1) {
        int tv = (t >= off) ? sh[t - off] : 0;
        __syncthreads();
        sh[t] += tv;
        __syncthreads();
    }
    if (gid < n) g_ptr[gid] = sh[t];
    if (t == 1023) g_bsum[blockIdx.x] = sh[1023];
}
__global__ void k_scan_sums(int nb) {
    __shared__ int sh[128];
    int t = threadIdx.x;
    int v = (t < nb) ? g_bsum[t] : 0;
    sh[t] = v;
    __syncthreads();
    #pragma unroll
    for (int off = 1; off < 128; off <<= 1) {
        int tv = (t >= off) ? sh[t - off] : 0;
        __syncthreads();
        sh[t] += tv;
        __syncthreads();
    }
    if (t < nb) g_bsum[t] = (t == 0) ? 0 : sh[t - 1];
}
__global__ void k_scan_add(int n) {
    int gid = blockIdx.x * 1024 + threadIdx.x;
    if (gid < n) {
        int v = g_ptr[gid] + g_bsum[blockIdx.x];
        g_ptr[gid] = v;
        g_cursor[gid] = v;
    }
}
__global__ void k_scatter(const int* __restrict__ rows, const int* __restrict__ cols,
                          const float* __restrict__ vals, int E) {
    int e = blockIdx.x * blockDim.x + threadIdx.x;
    if (e < E) {
        int r = __ldcs(rows + e);
        int pos = atomicAdd(&g_cursor[r], 1);
        g_cols[pos] = __ldcs(cols + e);
        g_vals[pos] = __ldcs(vals + e);
    }
}

// ---------------- W pre-round to tf32 ----------------
__global__ void k_prep_w(const float* __restrict__ W1, const float* __restrict__ W2) {
    int i = blockIdx.x * blockDim.x + threadIdx.x;
    g_Wt[i]         = __float_as_uint(f2tf32f(W1[i]));
    g_Wt[i + F * F] = __float_as_uint(f2tf32f(W2[i]));
}

// ---------------- tf32 wmma GEMM (A: fp32 or fp16), fp16 output ----------------
#define ALD 36
#define BLD 264
#define ASZ (64 * ALD)
#define BSZ (32 * BLD)
#define STAGE_F (ASZ + BSZ)
#define EPLD 264

__device__ __forceinline__ void cp16(uint32_t dst, const void* src) {
    asm volatile("cp.async.ca.shared.global [%0], [%1], 16;" :: "r"(dst), "l"(src));
}

template <int AHALF, int BNRELU>
__global__ void __launch_bounds__(256)
k_gemm_wmma(const void* __restrict__ Av, const uint32_t* __restrict__ Wt,
            __half* __restrict__ Ch, int M) {
    extern __shared__ float sm[];
    int tid = threadIdx.x;
    int wid = tid >> 5;
    int warp_row = wid >> 2;
    int warp_col = wid & 3;
    int row0 = blockIdx.x * 64;

    wmma::fragment<wmma::accumulator, 16, 16, 8, float> acc[2][4];
    #pragma unroll
    for (int i = 0; i < 2; i++)
        #pragma unroll
        for (int j = 0; j < 4; j++) wmma::fill_fragment(acc[i][j], 0.f);

    int a_r0 = AHALF ? (tid >> 2) : (tid >> 3);
    int a_c0 = AHALF ? ((tid & 3) * 8) : ((tid & 7) * 4);

    float4 areg[2];
    auto load_A = [&](int k0) {
        if constexpr (AHALF) {
            const __half* Ah = (const __half*)Av;
            int gr = row0 + a_r0;
            uint4 u = make_uint4(0, 0, 0, 0);
            if (gr < M) u = *(const uint4*)(Ah + (size_t)gr * F + k0 * 32 + a_c0);
            __half2* hp = reinterpret_cast<__half2*>(&u);
            float2 p0 = __half22float2(hp[0]);
            float2 p1 = __half22float2(hp[1]);
            float2 p2 = __half22float2(hp[2]);
            float2 p3 = __half22float2(hp[3]);
            areg[0] = make_float4(p0.x, p0.y, p1.x, p1.y);
            areg[1] = make_float4(p2.x, p2.y, p3.x, p3.y);
        } else {
            const float* Af = (const float*)Av;
            int gr0 = row0 + a_r0, gr1 = row0 + a_r0 + 32;
            areg[0] = (gr0 < M) ? *(const float4*)(Af + (size_t)gr0 * F + k0 * 32 + a_c0)
                                : make_float4(0.f, 0.f, 0.f, 0.f);
            areg[1] = (gr1 < M) ? *(const float4*)(Af + (size_t)gr1 * F + k0 * 32 + a_c0)
                                : make_float4(0.f, 0.f, 0.f, 0.f);
        }
        if constexpr (BNRELU) {
            int c = k0 * 32 + a_c0;
            if constexpr (AHALF) {
                float* v = reinterpret_cast<float*>(areg);
                #pragma unroll
                for (int i = 0; i < 8; i++)
                    v[i] = fmaxf(fmaf(v[i], g_a[c + i], g_b[c + i]), 0.f);
            } else {
                float a0 = g_a[c], a1 = g_a[c + 1], a2 = g_a[c + 2], a3 = g_a[c + 3];
                float b0 = g_b[c], b1 = g_b[c + 1], b2 = g_b[c + 2], b3 = g_b[c + 3];
                #pragma unroll
                for (int i = 0; i < 2; i++) {
                    areg[i].x = fmaxf(fmaf(areg[i].x, a0, b0), 0.f);
                    areg[i].y = fmaxf(fmaf(areg[i].y, a1, b1), 0.f);
                    areg[i].z = fmaxf(fmaf(areg[i].z, a2, b2), 0.f);
                    areg[i].w = fmaxf(fmaf(areg[i].w, a3, b3), 0.f);
                }
            }
        }
        float* v = reinterpret_cast<float*>(areg);
        #pragma unroll
        for (int i = 0; i < 8; i++) v[i] = f2tf32f(v[i]);
    };
    auto sts_A = [&](float* As) {
        if constexpr (AHALF) {
            *(float4*)(As + a_r0 * ALD + a_c0) = areg[0];
            *(float4*)(As + a_r0 * ALD + a_c0 + 4) = areg[1];
        } else {
            *(float4*)(As + a_r0 * ALD + a_c0) = areg[0];
            *(float4*)(As + (a_r0 + 32) * ALD + a_c0) = areg[1];
        }
    };
    auto cpB = [&](float* Bs, int k0) {
        uint32_t bbase = smem_u32(Bs);
        #pragma unroll
        for (int i = 0; i < 8; i++) {
            int idx = tid + i * 256;
            int r = idx >> 6;
            int c4 = (idx & 63) * 4;
            cp16(bbase + (uint32_t)(r * BLD + c4) * 4,
                 Wt + (size_t)(k0 * 32 + r) * F + c4);
        }
    };

    int buf = 0;
    load_A(0);
    sts_A(sm);
    cpB(sm + ASZ, 0);
    asm volatile("cp.async.commit_group;" ::: "memory");

    for (int k0 = 0; k0 < 8; k0++) {
        if (k0 < 7) load_A(k0 + 1);
        asm volatile("cp.async.wait_group 0;" ::: "memory");
        __syncthreads();
        float* As = sm + buf * STAGE_F;
        float* Bs = As + ASZ;
        if (k0 < 7) {
            float* Asn = sm + (buf ^ 1) * STAGE_F;
            sts_A(Asn);
            cpB(Asn + ASZ, k0 + 1);
            asm volatile("cp.async.commit_group;" ::: "memory");
        }
        #pragma unroll
        for (int kk = 0; kk < 4; kk++) {
            wmma::fragment<wmma::matrix_a, 16, 16, 8, wmma::precision::tf32, wmma::row_major> af[2];
            wmma::fragment<wmma::matrix_b, 16, 16, 8, wmma::precision::tf32, wmma::row_major> bf[4];
            #pragma unroll
            for (int i = 0; i < 2; i++)
                wmma::load_matrix_sync(af[i], As + (warp_row * 32 + i * 16) * ALD + kk * 8, ALD);
            #pragma unroll
            for (int j = 0; j < 4; j++)
                wmma::load_matrix_sync(bf[j], Bs + (kk * 8) * BLD + warp_col * 64 + j * 16, BLD);
            #pragma unroll
            for (int i = 0; i < 2; i++)
                #pragma unroll
                for (int j = 0; j < 4; j++)
                    wmma::mma_sync(acc[i][j], af[i], bf[j], acc[i][j]);
        }
        __syncthreads();
        buf ^= 1;
    }

    // epilogue: frags -> smem -> coalesced fp16 store
    float* ep = sm;
    #pragma unroll
    for (int i = 0; i < 2; i++)
        #pragma unroll
        for (int j = 0; j < 4; j++)
            wmma::store_matrix_sync(ep + (size_t)(warp_row * 32 + i * 16) * EPLD + warp_col * 64 + j * 16,
                                    acc[i][j], EPLD, wmma::mem_row_major);
    __syncthreads();

    #pragma unroll
    for (int it = 0; it < 8; it++) {
        int idx = tid + it * 256;
        int r = idx >> 5;
        int g = idx & 31;
        int grow = row0 + r;
        if (grow < M) {
            float4 v0 = *(float4*)(ep + r * EPLD + g * 8);
            float4 v1 = *(float4*)(ep + r * EPLD + g * 8 + 4);
            __half2 h[4];
            h[0] = __floats2half2_rn(v0.x, v0.y);
            h[1] = __floats2half2_rn(v0.z, v0.w);
            h[2] = __floats2half2_rn(v1.x, v1.y);
            h[3] = __floats2half2_rn(v1.z, v1.w);
            *(uint4*)(Ch + (size_t)grow * F + g * 8) = *reinterpret_cast<uint4*>(h);
        }
    }
}

// ---------------- SpMM (fp16 gather, evict_last via cache-hint policy) ----------------
// OUT16: write fp16 (SpMM1 -> H16); else fp32 (SpMM2 -> out). STATS: fused BN stats.
template <int OUT16, int STATS>
__global__ void __launch_bounds__(256)
k_spmm(const __half* __restrict__ Xh, void* __restrict__ Yv, int Nn) {
    __shared__ float ssum[256], ssumsq[256];
    int tid = threadIdx.x;
    if constexpr (STATS) {
        ssum[tid] = 0.f;
        ssumsq[tid] = 0.f;
        __syncthreads();
    }

    int gw = (blockIdx.x * 256 + tid) >> 5;
    int row = gw >> 1;
    int half = gw & 1;
    int lane = tid & 31;
    bool valid = (row < Nn);

    float4 acc = make_float4(0.f, 0.f, 0.f, 0.f);
    const __half* Xhh = Xh + half * 128;
    if (valid) {
        uint64_t pol = mk_policy_el();
        uint2 u = ldg_pol8(Xhh + (size_t)row * F + lane * 4, pol);   // self loop
        float2 f0 = __half22float2(*reinterpret_cast<const __half2*>(&u.x));
        float2 f1 = __half22float2(*reinterpret_cast<const __half2*>(&u.y));
        acc = make_float4(f0.x, f0.y, f1.x, f1.y);

        int e = g_ptr[row];
        int end = g_ptr[row + 1];
        while (e < end) {
            int m = end - e;
            int c = 0;
            float vv = 0.f;
            if (lane < m) { c = __ldcs(g_cols + e + lane); vv = __ldcs(g_vals + e + lane); }
            int cnt = m < 32 ? m : 32;
            #pragma unroll 8
            for (int j = 0; j < cnt; j++) {
                int cj = __shfl_sync(0xffffffffu, c, j);
                float vj = __shfl_sync(0xffffffffu, vv, j);
                uint2 un = ldg_pol8(Xhh + (size_t)cj * F + lane * 4, pol);
                float2 q0 = __half22float2(*reinterpret_cast<const __half2*>(&un.x));
                float2 q1 = __half22float2(*reinterpret_cast<const __half2*>(&un.y));
                acc.x = fmaf(vj, q0.x, acc.x);
                acc.y = fmaf(vj, q0.y, acc.y);
                acc.z = fmaf(vj, q1.x, acc.z);
                acc.w = fmaf(vj, q1.y, acc.w);
            }
            e += 32;
        }
        if constexpr (OUT16) {
            __half* Y = (__half*)Yv;
            __half2 h[2];
            h[0] = __floats2half2_rn(acc.x, acc.y);
            h[1] = __floats2half2_rn(acc.z, acc.w);
            __stcs((float2*)(Y + (size_t)row * F + half * 128 + lane * 4),
                   *reinterpret_cast<float2*>(h));
        } else {
            float* Y = (float*)Yv;
            __stcs((float4*)(Y + (size_t)row * F + half * 128 + lane * 4), acc);
        }
    }

    if constexpr (STATS) {
        if (valid) {
            int cb = half * 128 + lane * 4;
            atomicAdd(&ssum[cb + 0], acc.x);
            atomicAdd(&ssum[cb + 1], acc.y);
            atomicAdd(&ssum[cb + 2], acc.z);
            atomicAdd(&ssum[cb + 3], acc.w);
            atomicAdd(&ssumsq[cb + 0], acc.x * acc.x);
            atomicAdd(&ssumsq[cb + 1], acc.y * acc.y);
            atomicAdd(&ssumsq[cb + 2], acc.z * acc.z);
            atomicAdd(&ssumsq[cb + 3], acc.w * acc.w);
        }
        __syncthreads();
        atomicAdd(&g_stats[tid], ssum[tid]);
        atomicAdd(&g_stats[tid + 256], ssumsq[tid]);
    }
}

// ---------------- BN finalize ----------------
__global__ void k_finalize(int M, const float* __restrict__ gamma,
                           const float* __restrict__ beta) {
    int c = threadIdx.x;
    float invM = 1.f / (float)M;
    float m = g_stats[c] * invM;
    float var = g_stats[c + 256] * invM - m * m;
    float r = rsqrtf(var + 1e-5f);
    float a = gamma[c] * r;
    g_a[c] = a;
    g_b[c] = beta[c] - m * a;
}

// ---------------- launch ----------------
extern "C" void kernel_launch(void* const* d_in, const int* in_sizes, int n_in,
                              void* d_out, int out_size) {
    const float* feature = (const float*)d_in[0];
    const int*   rows    = (const int*)d_in[1];
    const int*   cols    = (const int*)d_in[2];
    const float* vals    = (const float*)d_in[3];
    const float* W1      = (const float*)d_in[4];
    const float* W2      = (const float*)d_in[5];
    const float* gamma   = (const float*)d_in[6];
    const float* beta    = (const float*)d_in[7];
    float* out = (float*)d_out;

    int N_ = in_sizes[0] / F;
    int E_ = in_sizes[1];

    __half *p_H16, *p_Xh;
    uint32_t* p_Wt;
    int* p_ptr;
    float* p_stats;
    cudaGetSymbolAddress((void**)&p_H16, g_H16);
    cudaGetSymbolAddress((void**)&p_Xh, g_Xh);
    cudaGetSymbolAddress((void**)&p_Wt, g_Wt);
    cudaGetSymbolAddress((void**)&p_ptr, g_ptr);
    cudaGetSymbolAddress((void**)&p_stats, g_stats);

    const int smem_bytes = 2 * STAGE_F * sizeof(float);
    cudaFuncSetAttribute(k_gemm_wmma<0, 0>, cudaFuncAttributeMaxDynamicSharedMemorySize, smem_bytes);
    cudaFuncSetAttribute(k_gemm_wmma<1, 1>, cudaFuncAttributeMaxDynamicSharedMemorySize, smem_bytes);

    static cudaStream_t s2 = nullptr;
    static cudaEvent_t evF = nullptr, evJ = nullptr;
    if (!s2) {
        cudaStreamCreateWithFlags(&s2, cudaStreamNonBlocking);
        cudaEventCreateWithFlags(&evF, cudaEventDisableTiming);
        cudaEventCreateWithFlags(&evJ, cudaEventDisableTiming);
    }

    int n_ptr = N_ + 1;
    int nb = (n_ptr + 1023) / 1024;
    int gtiles = (N_ + 63) / 64;
    int spmm_blocks = (2 * N_ * 32 + 255) / 256;

    // fork: CSR build concurrent with weight prep + GEMM1
    cudaEventRecord(evF, 0);
    cudaStreamWaitEvent(s2, evF, 0);

    cudaMemsetAsync(p_ptr, 0, (size_t)n_ptr * sizeof(int), s2);
    cudaMemsetAsync(p_stats, 0, 2 * F * sizeof(float), s2);
    k_hist<<<(E_ + 255) / 256, 256, 0, s2>>>(rows, E_);
    k_scan_block<<<nb, 1024, 0, s2>>>(n_ptr);
    k_scan_sums<<<1, 128, 0, s2>>>(nb);
    k_scan_add<<<nb, 1024, 0, s2>>>(n_ptr);
    k_scatter<<<(E_ + 255) / 256, 256, 0, s2>>>(rows, cols, vals, E_);
    cudaEventRecord(evJ, s2);

    k_prep_w<<<F * F / 256, 256>>>(W1, W2);
    k_gemm_wmma<0, 0><<<gtiles, 256, smem_bytes>>>(feature, p_Wt, p_Xh, N_);

    cudaStreamWaitEvent(0, evJ, 0);

    // H16 = (A+I)@support (fp16 out) + fused BN stats
    k_spmm<1, 1><<<spmm_blocks, 256>>>(p_Xh, p_H16, N_);
    k_finalize<<<1, 256>>>(N_, gamma, beta);
    // Xh = relu(BN(H16)) @ W2
    k_gemm_wmma<1, 1><<<gtiles, 256, smem_bytes>>>(p_H16, p_Wt + F * F, p_Xh, N_);
    // out = (A+I)@Xh  (fp32 out)
    k_spmm<0, 0><<<spmm_blocks, 256>>>(p_Xh, out, N_);
}

// round 10
// speedup vs baseline: 1.4020x; 1.3626x over previous
#include <cuda_runtime.h>
#include <cuda_bf16.h>
#include <cuda_fp16.h>
#include <mma.h>
#include <cstdint>
#include <math.h>

using namespace nvcuda;

#define F 256
#define MAXN 100000
#define MAXE 3200000

// ---------------- device scratch ----------------
__device__ __half g_H16[(size_t)MAXN * F];      // SpMM1 output (fp16, read by GEMM2)
__device__ __half g_Xh[(size_t)MAXN * F];       // fp16 copy of current GEMM output
__device__ int   g_ptr[MAXN + 1];
__device__ int   g_cursor[MAXN + 1];
__device__ int   g_cols[MAXE];
__device__ float g_vals[MAXE];
__device__ int   g_bsum[256];
__device__ float g_stats[2 * F];                // [0:256) sum, [256:512) sumsq
__device__ float g_a[F], g_b[F];
__device__ __half g_Wh[2 * F * F];              // W1, W2 pre-converted to fp16

__device__ __forceinline__ uint32_t smem_u32(const void* p) {
    uint32_t a;
    asm("{ .reg .u64 t; cvta.to.shared.u64 t, %1; cvt.u32.u64 %0, t; }" : "=r"(a) : "l"(p));
    return a;
}
// L2 evict_last policy
__device__ __forceinline__ uint64_t mk_policy_el() {
    uint64_t pol;
    asm volatile("createpolicy.fractional.L2::evict_last.b64 %0, 1.0;" : "=l"(pol));
    return pol;
}
__device__ __forceinline__ uint2 ldg_pol8(const void* p, uint64_t pol) {
    uint2 u;
    asm volatile("ld.global.nc.L2::cache_hint.v2.u32 {%0, %1}, [%2], %3;"
                 : "=r"(u.x), "=r"(u.y) : "l"(p), "l"(pol));
    return u;
}

// ---------------- CSR construction ----------------
__global__ void k_hist(const int* __restrict__ rows, int E) {
    int e = blockIdx.x * blockDim.x + threadIdx.x;
    if (e < E) atomicAdd(&g_ptr[__ldcs(rows + e) + 1], 1);
}
__global__ void k_scan_block(int n) {
    __shared__ int sh[1024];
    int t = threadIdx.x;
    int gid = blockIdx.x * 1024 + t;
    int v = (gid < n) ? g_ptr[gid] : 0;
    sh[t] = v;
    __syncthreads();
    #pragma unroll
    for (int off = 1; off < 1024; off <<= 1) {
        int tv = (t >= off) ? sh[t - off] : 0;
        __syncthreads();
        sh[t] += tv;
        __syncthreads();
    }
    if (gid < n) g_ptr[gid] = sh[t];
    if (t == 1023) g_bsum[blockIdx.x] = sh[1023];
}
__global__ void k_scan_sums(int nb) {
    __shared__ int sh[128];
    int t = threadIdx.x;
    int v = (t < nb) ? g_bsum[t] : 0;
    sh[t] = v;
    __syncthreads();
    #pragma unroll
    for (int off = 1; off < 128; off <<= 1) {
        int tv = (t >= off) ? sh[t - off] : 0;
        __syncthreads();
        sh[t] += tv;
        __syncthreads();
    }
    if (t < nb) g_bsum[t] = (t == 0) ? 0 : sh[t - 1];
}
__global__ void k_scan_add(int n) {
    int gid = blockIdx.x * 1024 + threadIdx.x;
    if (gid < n) {
        int v = g_ptr[gid] + g_bsum[blockIdx.x];
        g_ptr[gid] = v;
        g_cursor[gid] = v;
    }
}
__global__ void k_scatter(const int* __restrict__ rows, const int* __restrict__ cols,
                          const float* __restrict__ vals, int E) {
    int e = blockIdx.x * blockDim.x + threadIdx.x;
    if (e < E) {
        int r = __ldcs(rows + e);
        int pos = atomicAdd(&g_cursor[r], 1);
        g_cols[pos] = __ldcs(cols + e);
        g_vals[pos] = __ldcs(vals + e);
    }
}

// ---------------- W convert to fp16 ----------------
__global__ void k_prep_w(const float* __restrict__ W1, const float* __restrict__ W2) {
    int i = blockIdx.x * blockDim.x + threadIdx.x;
    g_Wh[i]         = __float2half_rn(W1[i]);
    g_Wh[i + F * F] = __float2half_rn(W2[i]);
}

// ---------------- fp16 wmma GEMM (A: fp32 or fp16), fp16 output ----------------
// CTA 64 rows x 256 cols, 8 warps (2x4), warp tile 32x64, K chunks of 32.
#define ALD_H 40
#define BLD_H 264
#define ASZ_H (64 * ALD_H)
#define BSZ_H (32 * BLD_H)
#define STAGE_H (ASZ_H + BSZ_H)
#define EPLD 264

__device__ __forceinline__ void cp16(uint32_t dst, const void* src) {
    asm volatile("cp.async.ca.shared.global [%0], [%1], 16;" :: "r"(dst), "l"(src));
}

template <int AHALF, int BNRELU>
__global__ void __launch_bounds__(256)
k_gemm_wmma(const void* __restrict__ Av, const __half* __restrict__ Wh,
            __half* __restrict__ Ch, int M) {
    extern __shared__ float sm[];
    __half* smh = reinterpret_cast<__half*>(sm);
    int tid = threadIdx.x;
    int wid = tid >> 5;
    int warp_row = wid >> 2;
    int warp_col = wid & 3;
    int row0 = blockIdx.x * 64;

    wmma::fragment<wmma::accumulator, 16, 16, 16, float> acc[2][4];
    #pragma unroll
    for (int i = 0; i < 2; i++)
        #pragma unroll
        for (int j = 0; j < 4; j++) wmma::fill_fragment(acc[i][j], 0.f);

    // fp32 A: thread covers (r, c..c+3) and (r+32, c..c+3), c=(tid&7)*4
    // fp16 A: thread covers (r, c..c+7), r=tid>>2, c=(tid&3)*8
    int a_r0 = AHALF ? (tid >> 2) : (tid >> 3);
    int a_c0 = AHALF ? ((tid & 3) * 8) : ((tid & 7) * 4);

    float areg[8];
    auto load_A = [&](int k0) {
        if constexpr (AHALF) {
            const __half* Ah = (const __half*)Av;
            int gr = row0 + a_r0;
            uint4 u = make_uint4(0, 0, 0, 0);
            if (gr < M) u = *(const uint4*)(Ah + (size_t)gr * F + k0 * 32 + a_c0);
            __half2* hp = reinterpret_cast<__half2*>(&u);
            #pragma unroll
            for (int i = 0; i < 4; i++) {
                float2 p = __half22float2(hp[i]);
                areg[i * 2] = p.x;
                areg[i * 2 + 1] = p.y;
            }
        } else {
            const float* Af = (const float*)Av;
            int gr0 = row0 + a_r0, gr1 = row0 + a_r0 + 32;
            float4 v0 = (gr0 < M) ? *(const float4*)(Af + (size_t)gr0 * F + k0 * 32 + a_c0)
                                  : make_float4(0.f, 0.f, 0.f, 0.f);
            float4 v1 = (gr1 < M) ? *(const float4*)(Af + (size_t)gr1 * F + k0 * 32 + a_c0)
                                  : make_float4(0.f, 0.f, 0.f, 0.f);
            areg[0] = v0.x; areg[1] = v0.y; areg[2] = v0.z; areg[3] = v0.w;
            areg[4] = v1.x; areg[5] = v1.y; areg[6] = v1.z; areg[7] = v1.w;
        }
        if constexpr (BNRELU) {
            int c = k0 * 32 + a_c0;
            if constexpr (AHALF) {
                #pragma unroll
                for (int i = 0; i < 8; i++)
                    areg[i] = fmaxf(fmaf(areg[i], g_a[c + i], g_b[c + i]), 0.f);
            } else {
                #pragma unroll
                for (int i = 0; i < 4; i++) {
                    float ga = g_a[c + i], gb = g_b[c + i];
                    areg[i]     = fmaxf(fmaf(areg[i],     ga, gb), 0.f);
                    areg[i + 4] = fmaxf(fmaf(areg[i + 4], ga, gb), 0.f);
                }
            }
        }
    };
    auto sts_A = [&](__half* As) {
        if constexpr (AHALF) {
            __half2 h[4];
            #pragma unroll
            for (int i = 0; i < 4; i++)
                h[i] = __floats2half2_rn(areg[i * 2], areg[i * 2 + 1]);
            *(uint4*)(As + a_r0 * ALD_H + a_c0) = *reinterpret_cast<uint4*>(h);
        } else {
            __half2 h0[2], h1[2];
            h0[0] = __floats2half2_rn(areg[0], areg[1]);
            h0[1] = __floats2half2_rn(areg[2], areg[3]);
            h1[0] = __floats2half2_rn(areg[4], areg[5]);
            h1[1] = __floats2half2_rn(areg[6], areg[7]);
            *(uint2*)(As + a_r0 * ALD_H + a_c0) = *reinterpret_cast<uint2*>(h0);
            *(uint2*)(As + (a_r0 + 32) * ALD_H + a_c0) = *reinterpret_cast<uint2*>(h1);
        }
    };
    // B tile: 32 k-rows x 256 n-cols fp16 = 16KB -> 1024 cp16 / 256 thr = 4 each
    auto cpB = [&](__half* Bs, int k0) {
        uint32_t bbase = smem_u32(Bs);
        #pragma unroll
        for (int i = 0; i < 4; i++) {
            int idx = tid + i * 256;
            int r = idx >> 5;               // 32 16B-slots per row
            int c8 = (idx & 31) * 8;        // col in halves
            cp16(bbase + (uint32_t)(r * BLD_H + c8) * 2,
                 Wh + (size_t)(k0 * 32 + r) * F + c8);
        }
    };

    int buf = 0;
    load_A(0);
    sts_A(smh);
    cpB(smh + ASZ_H, 0);
    asm volatile("cp.async.commit_group;" ::: "memory");

    for (int k0 = 0; k0 < 8; k0++) {
        if (k0 < 7) load_A(k0 + 1);
        asm volatile("cp.async.wait_group 0;" ::: "memory");
        __syncthreads();
        __half* As = smh + buf * STAGE_H;
        __half* Bs = As + ASZ_H;
        if (k0 < 7) {
            __half* Asn = smh + (buf ^ 1) * STAGE_H;
            sts_A(Asn);
            cpB(Asn + ASZ_H, k0 + 1);
            asm volatile("cp.async.commit_group;" ::: "memory");
        }
        #pragma unroll
        for (int kk = 0; kk < 2; kk++) {
            wmma::fragment<wmma::matrix_a, 16, 16, 16, __half, wmma::row_major> af[2];
            wmma::fragment<wmma::matrix_b, 16, 16, 16, __half, wmma::row_major> bf[4];
            #pragma unroll
            for (int i = 0; i < 2; i++)
                wmma::load_matrix_sync(af[i], As + (warp_row * 32 + i * 16) * ALD_H + kk * 16, ALD_H);
            #pragma unroll
            for (int j = 0; j < 4; j++)
                wmma::load_matrix_sync(bf[j], Bs + (kk * 16) * BLD_H + warp_col * 64 + j * 16, BLD_H);
            #pragma unroll
            for (int i = 0; i < 2; i++)
                #pragma unroll
                for (int j = 0; j < 4; j++)
                    wmma::mma_sync(acc[i][j], af[i], bf[j], acc[i][j]);
        }
        __syncthreads();
        buf ^= 1;
    }

    // epilogue: frags -> smem(float) -> coalesced fp16 store
    float* ep = sm;
    #pragma unroll
    for (int i = 0; i < 2; i++)
        #pragma unroll
        for (int j = 0; j < 4; j++)
            wmma::store_matrix_sync(ep + (size_t)(warp_row * 32 + i * 16) * EPLD + warp_col * 64 + j * 16,
                                    acc[i][j], EPLD, wmma::mem_row_major);
    __syncthreads();

    #pragma unroll
    for (int it = 0; it < 8; it++) {
        int idx = tid + it * 256;
        int r = idx >> 5;
        int g = idx & 31;
        int grow = row0 + r;
        if (grow < M) {
            float4 v0 = *(float4*)(ep + r * EPLD + g * 8);
            float4 v1 = *(float4*)(ep + r * EPLD + g * 8 + 4);
            __half2 h[4];
            h[0] = __floats2half2_rn(v0.x, v0.y);
            h[1] = __floats2half2_rn(v0.z, v0.w);
            h[2] = __floats2half2_rn(v1.x, v1.y);
            h[3] = __floats2half2_rn(v1.z, v1.w);
            *(uint4*)(Ch + (size_t)grow * F + g * 8) = *reinterpret_cast<uint4*>(h);
        }
    }
}

// ---------------- SpMM (fp16 gather, evict_last) ----------------
template <int OUT16, int STATS>
__global__ void __launch_bounds__(256)
k_spmm(const __half* __restrict__ Xh, void* __restrict__ Yv, int Nn) {
    __shared__ float ssum[256], ssumsq[256];
    int tid = threadIdx.x;
    if constexpr (STATS) {
        ssum[tid] = 0.f;
        ssumsq[tid] = 0.f;
        __syncthreads();
    }

    int gw = (blockIdx.x * 256 + tid) >> 5;
    int row = gw >> 1;
    int half = gw & 1;
    int lane = tid & 31;
    bool valid = (row < Nn);

    float4 acc = make_float4(0.f, 0.f, 0.f, 0.f);
    const __half* Xhh = Xh + half * 128;
    if (valid) {
        uint64_t pol = mk_policy_el();
        uint2 u = ldg_pol8(Xhh + (size_t)row * F + lane * 4, pol);   // self loop
        float2 f0 = __half22float2(*reinterpret_cast<const __half2*>(&u.x));
        float2 f1 = __half22float2(*reinterpret_cast<const __half2*>(&u.y));
        acc = make_float4(f0.x, f0.y, f1.x, f1.y);

        int e = g_ptr[row];
        int end = g_ptr[row + 1];
        while (e < end) {
            int m = end - e;
            int c = 0;
            float vv = 0.f;
            if (lane < m) { c = __ldcs(g_cols + e + lane); vv = __ldcs(g_vals + e + lane); }
            int cnt = m < 32 ? m : 32;
            #pragma unroll 8
            for (int j = 0; j < cnt; j++) {
                int cj = __shfl_sync(0xffffffffu, c, j);
                float vj = __shfl_sync(0xffffffffu, vv, j);
                uint2 un = ldg_pol8(Xhh + (size_t)cj * F + lane * 4, pol);
                float2 q0 = __half22float2(*reinterpret_cast<const __half2*>(&un.x));
                float2 q1 = __half22float2(*reinterpret_cast<const __half2*>(&un.y));
                acc.x = fmaf(vj, q0.x, acc.x);
                acc.y = fmaf(vj, q0.y, acc.y);
                acc.z = fmaf(vj, q1.x, acc.z);
                acc.w = fmaf(vj, q1.y, acc.w);
            }
            e += 32;
        }
        if constexpr (OUT16) {
            __half* Y = (__half*)Yv;
            __half2 h[2];
            h[0] = __floats2half2_rn(acc.x, acc.y);
            h[1] = __floats2half2_rn(acc.z, acc.w);
            __stcs((float2*)(Y + (size_t)row * F + half * 128 + lane * 4),
                   *reinterpret_cast<float2*>(h));
        } else {
            float* Y = (float*)Yv;
            __stcs((float4*)(Y + (size_t)row * F + half * 128 + lane * 4), acc);
        }
    }

    if constexpr (STATS) {
        if (valid) {
            int cb = half * 128 + lane * 4;
            atomicAdd(&ssum[cb + 0], acc.x);
            atomicAdd(&ssum[cb + 1], acc.y);
            atomicAdd(&ssum[cb + 2], acc.z);
            atomicAdd(&ssum[cb + 3], acc.w);
            atomicAdd(&ssumsq[cb + 0], acc.x * acc.x);
            atomicAdd(&ssumsq[cb + 1], acc.y * acc.y);
            atomicAdd(&ssumsq[cb + 2], acc.z * acc.z);
            atomicAdd(&ssumsq[cb + 3], acc.w * acc.w);
        }
        __syncthreads();
        atomicAdd(&g_stats[tid], ssum[tid]);
        atomicAdd(&g_stats[tid + 256], ssumsq[tid]);
    }
}

// ---------------- BN finalize ----------------
__global__ void k_finalize(int M, const float* __restrict__ gamma,
                           const float* __restrict__ beta) {
    int c = threadIdx.x;
    float invM = 1.f / (float)M;
    float m = g_stats[c] * invM;
    float var = g_stats[c + 256] * invM - m * m;
    float r = rsqrtf(var + 1e-5f);
    float a = gamma[c] * r;
    g_a[c] = a;
    g_b[c] = beta[c] - m * a;
}

// ---------------- launch ----------------
extern "C" void kernel_launch(void* const* d_in, const int* in_sizes, int n_in,
                              void* d_out, int out_size) {
    const float* feature = (const float*)d_in[0];
    const int*   rows    = (const int*)d_in[1];
    const int*   cols    = (const int*)d_in[2];
    const float* vals    = (const float*)d_in[3];
    const float* W1      = (const float*)d_in[4];
    const float* W2      = (const float*)d_in[5];
    const float* gamma   = (const float*)d_in[6];
    const float* beta    = (const float*)d_in[7];
    float* out = (float*)d_out;

    int N_ = in_sizes[0] / F;
    int E_ = in_sizes[1];

    __half *p_H16, *p_Xh, *p_Wh;
    int* p_ptr;
    float* p_stats;
    cudaGetSymbolAddress((void**)&p_H16, g_H16);
    cudaGetSymbolAddress((void**)&p_Xh, g_Xh);
    cudaGetSymbolAddress((void**)&p_Wh, g_Wh);
    cudaGetSymbolAddress((void**)&p_ptr, g_ptr);
    cudaGetSymbolAddress((void**)&p_stats, g_stats);

    const int smem_bytes = 64 * EPLD * sizeof(float) > 2 * STAGE_H * (int)sizeof(__half)
                         ? 64 * EPLD * sizeof(float) : 2 * STAGE_H * (int)sizeof(__half);
    cudaFuncSetAttribute(k_gemm_wmma<0, 0>, cudaFuncAttributeMaxDynamicSharedMemorySize, smem_bytes);
    cudaFuncSetAttribute(k_gemm_wmma<1, 1>, cudaFuncAttributeMaxDynamicSharedMemorySize, smem_bytes);

    static cudaStream_t s2 = nullptr;
    static cudaEvent_t evF = nullptr, evJ = nullptr;
    if (!s2) {
        cudaStreamCreateWithFlags(&s2, cudaStreamNonBlocking);
        cudaEventCreateWithFlags(&evF, cudaEventDisableTiming);
        cudaEventCreateWithFlags(&evJ, cudaEventDisableTiming);
    }

    int n_ptr = N_ + 1;
    int nb = (n_ptr + 1023) / 1024;
    int gtiles = (N_ + 63) / 64;
    int spmm_blocks = (2 * N_ * 32 + 255) / 256;

    // fork: CSR build concurrent with weight prep + GEMM1
    cudaEventRecord(evF, 0);
    cudaStreamWaitEvent(s2, evF, 0);

    cudaMemsetAsync(p_ptr, 0, (size_t)n_ptr * sizeof(int), s2);
    cudaMemsetAsync(p_stats, 0, 2 * F * sizeof(float), s2);
    k_hist<<<(E_ + 255) / 256, 256, 0, s2>>>(rows, E_);
    k_scan_block<<<nb, 1024, 0, s2>>>(n_ptr);
    k_scan_sums<<<1, 128, 0, s2>>>(nb);
    k_scan_add<<<nb, 1024, 0, s2>>>(n_ptr);
    k_scatter<<<(E_ + 255) / 256, 256, 0, s2>>>(rows, cols, vals, E_);
    cudaEventRecord(evJ, s2);

    k_prep_w<<<F * F / 256, 256>>>(W1, W2);
    k_gemm_wmma<0, 0><<<gtiles, 256, smem_bytes>>>(feature, p_Wh, p_Xh, N_);

    cudaStreamWaitEvent(0, evJ, 0);

    // H16 = (A+I)@support (fp16 out) + fused BN stats
    k_spmm<1, 1><<<spmm_blocks, 256>>>(p_Xh, p_H16, N_);
    k_finalize<<<1, 256>>>(N_, gamma, beta);
    // Xh = relu(BN(H16)) @ W2
    k_gemm_wmma<1, 1><<<gtiles, 256, smem_bytes>>>(p_H16, p_Wh + F * F, p_Xh, N_);
    // out = (A+I)@Xh  (fp32 out)
    k_spmm<0, 0><<<spmm_blocks, 256>>>(p_Xh, out, N_);
}